// round 4
// baseline (speedup 1.0000x reference)
#include <cuda_runtime.h>
#include <cstdint>

#define T_STEPS 4096
#define IN_DIM  512
#define H_DIM   2048
#define OUT_DIM 4

#define RT 16            // row tiles
#define CT 8             // col tiles
#define NCTA (RT*CT)     // 128 persistent CTAs
#define RPT (H_DIM/RT)   // 128 rows per tile
#define CPT (H_DIM/CT)   // 256 cols per tile (== blockDim.x)
#define TPB 256
#define HEBB_SMEM_BYTES (RPT*CPT*4)   // 131072

// ---------------- device scratch (static; no allocs allowed) ----------------
__device__ float g_xz[(size_t)T_STEPS * H_DIM];
__device__ float g_xr[(size_t)T_STEPS * H_DIM];
__device__ float g_xh[(size_t)T_STEPS * H_DIM];
__device__ float g_hbuf[(size_t)(T_STEPS + 1) * H_DIM];
__device__ float g_Pz[2][RT][H_DIM];
__device__ float g_Pr[2][RT][H_DIM];
__device__ float g_Ph[2][RT][H_DIM];

__device__ unsigned g_barCnt = 0;
__device__ volatile unsigned g_barGen = 0;

__device__ __forceinline__ void grid_barrier() {
    __syncthreads();
    if (threadIdx.x == 0) {
        unsigned gen = g_barGen;
        __threadfence();
        unsigned arr = atomicAdd(&g_barCnt, 1u);
        if (arr == NCTA - 1) {
            g_barCnt = 0;
            __threadfence();
            g_barGen = gen + 1;
        } else {
            while (g_barGen == gen) { __nanosleep(32); }
            __threadfence();
        }
    }
    __syncthreads();
}

__device__ __forceinline__ float sigm(float x) { return 1.0f / (1.0f + expf(-x)); }

// ---------------- init: h0 -> g_hbuf[0] ----------------
__global__ void init_kernel(const float* __restrict__ h0) {
    int i = blockIdx.x * blockDim.x + threadIdx.x;
    if (i < H_DIM) g_hbuf[i] = h0[i];
}

// ---------------- input projections: x @ W_m + b_m ----------------
__global__ void __launch_bounds__(256)
xproj_kernel(const float* __restrict__ x,
             const float* __restrict__ Wz, const float* __restrict__ bz,
             const float* __restrict__ Wr, const float* __restrict__ br,
             const float* __restrict__ Wh, const float* __restrict__ bh) {
    const int mat = blockIdx.z;
    const float* W = (mat == 0) ? Wz : (mat == 1) ? Wr : Wh;
    const float* b = (mat == 0) ? bz : (mat == 1) ? br : bh;
    float* outp    = (mat == 0) ? g_xz : (mat == 1) ? g_xr : g_xh;

    const int bn = blockIdx.x * 64;   // hidden cols
    const int bm = blockIdx.y * 64;   // time rows

    __shared__ float As[16][65];      // As[k][m]
    __shared__ float Bs[16][64];      // Bs[k][n]

    const int tid = threadIdx.x;
    const int ty = tid >> 4, tx = tid & 15;
    const int mfrag = ty * 4, nfrag = tx * 4;

    float acc[4][4] = {};

    for (int k0 = 0; k0 < IN_DIM; k0 += 16) {
        {   // load A tile 64x16 (one float4/thread)
            int row = tid >> 2, q = tid & 3;
            float4 v = *reinterpret_cast<const float4*>(
                x + (size_t)(bm + row) * IN_DIM + k0 + q * 4);
            As[q * 4 + 0][row] = v.x; As[q * 4 + 1][row] = v.y;
            As[q * 4 + 2][row] = v.z; As[q * 4 + 3][row] = v.w;
            // load B tile 16x64 (one float4/thread)
            int krow = tid >> 4, c4 = (tid & 15) * 4;
            float4 w = *reinterpret_cast<const float4*>(
                W + (size_t)(k0 + krow) * H_DIM + bn + c4);
            *reinterpret_cast<float4*>(&Bs[krow][c4]) = w;
        }
        __syncthreads();
        #pragma unroll
        for (int k = 0; k < 16; k++) {
            float a0 = As[k][mfrag + 0], a1 = As[k][mfrag + 1];
            float a2 = As[k][mfrag + 2], a3 = As[k][mfrag + 3];
            float4 bv = *reinterpret_cast<const float4*>(&Bs[k][nfrag]);
            acc[0][0] = fmaf(a0, bv.x, acc[0][0]); acc[0][1] = fmaf(a0, bv.y, acc[0][1]);
            acc[0][2] = fmaf(a0, bv.z, acc[0][2]); acc[0][3] = fmaf(a0, bv.w, acc[0][3]);
            acc[1][0] = fmaf(a1, bv.x, acc[1][0]); acc[1][1] = fmaf(a1, bv.y, acc[1][1]);
            acc[1][2] = fmaf(a1, bv.z, acc[1][2]); acc[1][3] = fmaf(a1, bv.w, acc[1][3]);
            acc[2][0] = fmaf(a2, bv.x, acc[2][0]); acc[2][1] = fmaf(a2, bv.y, acc[2][1]);
            acc[2][2] = fmaf(a2, bv.z, acc[2][2]); acc[2][3] = fmaf(a2, bv.w, acc[2][3]);
            acc[3][0] = fmaf(a3, bv.x, acc[3][0]); acc[3][1] = fmaf(a3, bv.y, acc[3][1]);
            acc[3][2] = fmaf(a3, bv.z, acc[3][2]); acc[3][3] = fmaf(a3, bv.w, acc[3][3]);
        }
        __syncthreads();
    }
    #pragma unroll
    for (int e = 0; e < 4; e++) {
        size_t rowoff = (size_t)(bm + mfrag + e) * H_DIM;
        #pragma unroll
        for (int f = 0; f < 4; f++) {
            int n = bn + nfrag + f;
            outp[rowoff + n] = acc[e][f] + b[n];
        }
    }
}

// ---------------- persistent scan ----------------
__global__ void __launch_bounds__(TPB, 1)
scan_kernel(const float* __restrict__ Uz, const float* __restrict__ Ur,
            const float* __restrict__ Uh, const float* __restrict__ alpha,
            const float* __restrict__ hebb0, const float* __restrict__ eta_p,
            float* __restrict__ out_hT, float* __restrict__ out_hebb) {
    extern __shared__ float s_hebb[];           // [RPT][CPT]
    const int tid = threadIdx.x;
    const int rt = blockIdx.x >> 3;
    const int ct = blockIdx.x & 7;
    const int i0 = rt * RPT;
    const int j0 = ct * CPT;
    const int j = j0 + tid;

    const float eta = eta_p[0];
    const float om = 1.0f - eta;

    __shared__ float sh_h[RPT], sh_rh[RPT], sh_hm1[RPT];

    // load hebb tile into SMEM
    for (int idx = tid; idx < RPT * (CPT / 4); idx += TPB) {
        int row = idx >> 6;        // CPT/4 = 64
        int c4 = idx & 63;
        float4 v = *reinterpret_cast<const float4*>(
            hebb0 + (size_t)(i0 + row) * H_DIM + j0 + c4 * 4);
        *reinterpret_cast<float4*>(s_hebb + row * CPT + c4 * 4) = v;
    }

    for (int t = 0; t < T_STEPS; t++) {
        const int p = t & 1;
        // ---- phase 1: reconstruct h_t rows for this tile ----
        if (tid < RPT) {
            int i = i0 + tid;
            float h, hp = 0.f;
            if (t == 0) {
                h = g_hbuf[i];
            } else {
                const int q = p ^ 1;
                float az = g_xz[(size_t)(t - 1) * H_DIM + i];
                float ah = g_xh[(size_t)(t - 1) * H_DIM + i];
                #pragma unroll
                for (int k = 0; k < RT; k++) { az += g_Pz[q][k][i]; ah += g_Ph[q][k][i]; }
                float z = sigm(az);
                float ht = tanhf(ah);
                hp = g_hbuf[(size_t)(t - 1) * H_DIM + i];
                h = (1.0f - z) * hp + z * ht;
                if (ct == 0) g_hbuf[(size_t)t * H_DIM + i] = h;
            }
            sh_h[tid] = h;
            sh_hm1[tid] = hp;
        }
        __syncthreads();
        // z/r GEMV partials over this tile
        {
            float az = 0.f, ar = 0.f;
            const float* uz = Uz + (size_t)i0 * H_DIM + j;
            const float* ur = Ur + (size_t)i0 * H_DIM + j;
            #pragma unroll 8
            for (int i = 0; i < RPT; i++) {
                float hv = sh_h[i];
                az = fmaf(hv, uz[(size_t)i * H_DIM], az);
                ar = fmaf(hv, ur[(size_t)i * H_DIM], ar);
            }
            g_Pz[p][rt][j] = az;
            g_Pr[p][rt][j] = ar;
        }
        grid_barrier();

        // ---- phase 2: r, rh, fused lazy-hebb update + (Uh + alpha*hebb) GEMV ----
        if (tid < RPT) {
            int i = i0 + tid;
            float arv = g_xr[(size_t)t * H_DIM + i];
            #pragma unroll
            for (int k = 0; k < RT; k++) arv += g_Pr[p][k][i];
            float r = sigm(arv);
            sh_rh[tid] = r * sh_h[tid];
        }
        __syncthreads();
        {
            float acc = 0.f;
            const float hj = g_hbuf[(size_t)t * H_DIM + j];
            const float* uh = Uh + (size_t)i0 * H_DIM + j;
            const float* al = alpha + (size_t)i0 * H_DIM + j;
            if (t > 0) {
                const float ehj = eta * hj;
                #pragma unroll 8
                for (int i = 0; i < RPT; i++) {
                    float v = s_hebb[i * CPT + tid];
                    v = fmaf(om, v, ehj * sh_hm1[i]);
                    s_hebb[i * CPT + tid] = v;
                    acc = fmaf(sh_rh[i],
                               fmaf(al[(size_t)i * H_DIM], v, uh[(size_t)i * H_DIM]),
                               acc);
                }
            } else {
                #pragma unroll 8
                for (int i = 0; i < RPT; i++) {
                    float v = s_hebb[i * CPT + tid];
                    acc = fmaf(sh_rh[i],
                               fmaf(al[(size_t)i * H_DIM], v, uh[(size_t)i * H_DIM]),
                               acc);
                }
            }
            g_Ph[p][rt][j] = acc;
        }
        grid_barrier();
    }

    // ---- finalize: h_T, hT out, hebbT out (apply last pending update) ----
    {
        const int q = (T_STEPS - 1) & 1;
        if (tid < RPT) {
            int i = i0 + tid;
            float az = g_xz[(size_t)(T_STEPS - 1) * H_DIM + i];
            float ah = g_xh[(size_t)(T_STEPS - 1) * H_DIM + i];
            #pragma unroll
            for (int k = 0; k < RT; k++) { az += g_Pz[q][k][i]; ah += g_Ph[q][k][i]; }
            float z = sigm(az);
            float ht = tanhf(ah);
            float hp = g_hbuf[(size_t)(T_STEPS - 1) * H_DIM + i];
            float h = (1.0f - z) * hp + z * ht;
            if (ct == 0) {
                g_hbuf[(size_t)T_STEPS * H_DIM + i] = h;
                out_hT[i] = h;
            }
            sh_hm1[tid] = hp;   // h_{T-1}
        }
        grid_barrier();
        const float hTj = g_hbuf[(size_t)T_STEPS * H_DIM + j];
        const float ehj = eta * hTj;
        for (int rl = 0; rl < RPT; rl++) {
            float v = fmaf(om, s_hebb[rl * CPT + tid], ehj * sh_hm1[rl]);
            out_hebb[(size_t)(i0 + rl) * H_DIM + j] = v;
        }
    }
}

// ---------------- output projection: y @ Wo + bo ----------------
__global__ void __launch_bounds__(256)
out_gemm_kernel(const float* __restrict__ Wo, const float* __restrict__ bo,
                float* __restrict__ out) {
    const int t = blockIdx.x;
    const int tid = threadIdx.x;
    const float* y = g_hbuf + (size_t)(t + 1) * H_DIM;   // y[t] = h_{t+1}
    float a0 = 0.f, a1 = 0.f, a2 = 0.f, a3 = 0.f;
    for (int jj = tid; jj < H_DIM; jj += 256) {
        float hv = y[jj];
        float4 w = *reinterpret_cast<const float4*>(Wo + (size_t)jj * OUT_DIM);
        a0 = fmaf(hv, w.x, a0); a1 = fmaf(hv, w.y, a1);
        a2 = fmaf(hv, w.z, a2); a3 = fmaf(hv, w.w, a3);
    }
    #pragma unroll
    for (int off = 16; off > 0; off >>= 1) {
        a0 += __shfl_down_sync(0xffffffffu, a0, off);
        a1 += __shfl_down_sync(0xffffffffu, a1, off);
        a2 += __shfl_down_sync(0xffffffffu, a2, off);
        a3 += __shfl_down_sync(0xffffffffu, a3, off);
    }
    __shared__ float red[8][4];
    const int wid = tid >> 5, lane = tid & 31;
    if (lane == 0) { red[wid][0] = a0; red[wid][1] = a1; red[wid][2] = a2; red[wid][3] = a3; }
    __syncthreads();
    if (tid < OUT_DIM) {
        float s = bo[tid];
        #pragma unroll
        for (int w = 0; w < 8; w++) s += red[w][tid];
        out[(size_t)t * OUT_DIM + tid] = s;
    }
}

// ---------------- JAX threefry2x32 (partitionable) / fold_in / categorical ----------------
__device__ __forceinline__ uint32_t rotl32(uint32_t x, int r) {
    return (x << r) | (x >> (32 - r));
}

__device__ __forceinline__ void threefry2x32(uint32_t k0, uint32_t k1,
                                             uint32_t x0, uint32_t x1,
                                             uint32_t& o0, uint32_t& o1) {
    uint32_t ks2 = k0 ^ k1 ^ 0x1BD11BDAu;
    uint32_t ks[3] = {k0, k1, ks2};
    const int r0[4] = {13, 15, 26, 6};
    const int r1[4] = {17, 29, 16, 24};
    x0 += k0; x1 += k1;
    #pragma unroll
    for (int d = 0; d < 5; d++) {
        const int* rr = (d & 1) ? r1 : r0;
        #pragma unroll
        for (int qv = 0; qv < 4; qv++) { x0 += x1; x1 = rotl32(x1, rr[qv]); x1 ^= x0; }
        x0 += ks[(d + 1) % 3];
        x1 += ks[(d + 2) % 3] + (uint32_t)(d + 1);
    }
    o0 = x0; o1 = x1;
}

__device__ __forceinline__ float gumbel_from_bits(uint32_t bits) {
    float f = __uint_as_float((bits >> 9) | 0x3f800000u) - 1.0f;
    const float tiny = 1.17549435e-38f;            // finfo(f32).tiny
    float u = f * (1.0f - tiny) + tiny;
    u = fmaxf(tiny, u);
    return -logf(-logf(u));
}

// jax_threefry_partitionable=True (default since JAX 0.4.30):
// element m of random_bits gets 64-bit counter m; block = threefry2x32(key, hi32(m), lo32(m));
// 32-bit output = b0 ^ b1.
__global__ void action_kernel(const float* __restrict__ logits,
                              float* __restrict__ act_out,
                              const int* __restrict__ seed_p) {
    int t = blockIdx.x * blockDim.x + threadIdx.x;
    if (t >= T_STEPS) return;
    int seed = seed_p[0];
    uint32_t k0 = (seed < 0) ? 0xFFFFFFFFu : 0u;   // hi word of int seed
    uint32_t k1 = (uint32_t)seed;
    uint32_t fk0, fk1;
    threefry2x32(k0, k1, 0u, 1u, fk0, fk1);        // fold_in(key, 1)

    uint32_t b[2];
    #pragma unroll
    for (int c = 0; c < 2; c++) {
        uint32_t m = 2u * (uint32_t)t + (uint32_t)c;  // flat index < 8192, hi32 = 0
        uint32_t o0, o1;
        threefry2x32(fk0, fk1, 0u, m, o0, o1);
        b[c] = o0 ^ o1;
    }
    float v0 = logits[(size_t)t * OUT_DIM + 0] + gumbel_from_bits(b[0]);
    float v1 = logits[(size_t)t * OUT_DIM + 1] + gumbel_from_bits(b[1]);
    act_out[t] = (v1 > v0) ? 1.0f : 0.0f;          // argmax, first-index ties
}

// ---------------- launch ----------------
extern "C" void kernel_launch(void* const* d_in, const int* in_sizes, int n_in,
                              void* d_out, int out_size) {
    const float* x     = (const float*)d_in[0];
    const float* h0    = (const float*)d_in[1];
    const float* hebb0 = (const float*)d_in[2];
    const float* Wz    = (const float*)d_in[3];
    const float* Uz    = (const float*)d_in[4];
    const float* bz    = (const float*)d_in[5];
    const float* Wr    = (const float*)d_in[6];
    const float* Ur    = (const float*)d_in[7];
    const float* br    = (const float*)d_in[8];
    const float* Wh    = (const float*)d_in[9];
    const float* Uh    = (const float*)d_in[10];
    const float* bh    = (const float*)d_in[11];
    const float* alpha = (const float*)d_in[12];
    const float* eta   = (const float*)d_in[13];
    const float* Wo    = (const float*)d_in[14];
    const float* bo    = (const float*)d_in[15];
    const int*   seed  = (const int*)d_in[16];
    float* out = (float*)d_out;

    // output layout (fp32): [0,16384) output | [16384,20480) action |
    //                       [20480,22528) hT | [22528, +4194304) hebbT
    float* out_output = out;
    float* out_action = out + (size_t)T_STEPS * OUT_DIM;
    float* out_hT     = out_action + T_STEPS;
    float* out_hebb   = out_hT + H_DIM;

    cudaFuncSetAttribute(scan_kernel,
                         cudaFuncAttributeMaxDynamicSharedMemorySize,
                         HEBB_SMEM_BYTES);

    init_kernel<<<(H_DIM + 255) / 256, 256>>>(h0);

    dim3 gproj(H_DIM / 64, T_STEPS / 64, 3);
    xproj_kernel<<<gproj, 256>>>(x, Wz, bz, Wr, br, Wh, bh);

    scan_kernel<<<NCTA, TPB, HEBB_SMEM_BYTES>>>(Uz, Ur, Uh, alpha, hebb0, eta,
                                                out_hT, out_hebb);

    out_gemm_kernel<<<T_STEPS, 256>>>(Wo, bo, out_output);

    action_kernel<<<(T_STEPS + 255) / 256, 256>>>(out_output, out_action, seed);
}

// round 5
// speedup vs baseline: 1.2160x; 1.2160x over previous
#include <cuda_runtime.h>
#include <cstdint>

#define T_STEPS 4096
#define IN_DIM  512
#define H_DIM   2048
#define OUT_DIM 4

#define RT 64            // row tiles (reduction split)
#define CT 2             // col tiles
#define NCTA (RT*CT)     // 128 persistent CTAs
#define RPT (H_DIM/RT)   // 32 rows per tile
#define CPT (H_DIM/CT)   // 1024 cols per tile
#define TPB 256          // 4 cols per thread (float4)
#define HEBB_SMEM_BYTES (RPT*CPT*4)   // 131072

// ---------------- device scratch (static; no allocs allowed) ----------------
__device__ float g_xz[(size_t)T_STEPS * H_DIM];
__device__ float g_xr[(size_t)T_STEPS * H_DIM];
__device__ float g_xh[(size_t)T_STEPS * H_DIM];
__device__ float g_hbuf[(size_t)(T_STEPS + 1) * H_DIM];
__device__ float g_Pz[2][RT][H_DIM];
__device__ float g_Pr[2][RT][H_DIM];
__device__ float g_Ph[2][RT][H_DIM];

__device__ unsigned g_barCnt = 0;
__device__ volatile unsigned g_barGen = 0;

__device__ __forceinline__ void grid_barrier() {
    __syncthreads();
    if (threadIdx.x == 0) {
        unsigned gen = g_barGen;
        __threadfence();
        unsigned arr = atomicAdd(&g_barCnt, 1u);
        if (arr == NCTA - 1) {
            g_barCnt = 0;
            __threadfence();
            g_barGen = gen + 1;
        } else {
            while (g_barGen == gen) { __nanosleep(32); }
            __threadfence();
        }
    }
    __syncthreads();
}

__device__ __forceinline__ float sigm(float x) { return 1.0f / (1.0f + expf(-x)); }

// ---------------- init: h0 -> g_hbuf[0] ----------------
__global__ void init_kernel(const float* __restrict__ h0) {
    int i = blockIdx.x * blockDim.x + threadIdx.x;
    if (i < H_DIM) g_hbuf[i] = h0[i];
}

// ---------------- input projections: x @ W_m + b_m ----------------
__global__ void __launch_bounds__(256)
xproj_kernel(const float* __restrict__ x,
             const float* __restrict__ Wz, const float* __restrict__ bz,
             const float* __restrict__ Wr, const float* __restrict__ br,
             const float* __restrict__ Wh, const float* __restrict__ bh) {
    const int mat = blockIdx.z;
    const float* W = (mat == 0) ? Wz : (mat == 1) ? Wr : Wh;
    const float* b = (mat == 0) ? bz : (mat == 1) ? br : bh;
    float* outp    = (mat == 0) ? g_xz : (mat == 1) ? g_xr : g_xh;

    const int bn = blockIdx.x * 64;   // hidden cols
    const int bm = blockIdx.y * 64;   // time rows

    __shared__ float As[16][65];      // As[k][m]
    __shared__ float Bs[16][64];      // Bs[k][n]

    const int tid = threadIdx.x;
    const int ty = tid >> 4, tx = tid & 15;
    const int mfrag = ty * 4, nfrag = tx * 4;

    float acc[4][4] = {};

    for (int k0 = 0; k0 < IN_DIM; k0 += 16) {
        {
            int row = tid >> 2, q = tid & 3;
            float4 v = *reinterpret_cast<const float4*>(
                x + (size_t)(bm + row) * IN_DIM + k0 + q * 4);
            As[q * 4 + 0][row] = v.x; As[q * 4 + 1][row] = v.y;
            As[q * 4 + 2][row] = v.z; As[q * 4 + 3][row] = v.w;
            int krow = tid >> 4, c4 = (tid & 15) * 4;
            float4 w = *reinterpret_cast<const float4*>(
                W + (size_t)(k0 + krow) * H_DIM + bn + c4);
            *reinterpret_cast<float4*>(&Bs[krow][c4]) = w;
        }
        __syncthreads();
        #pragma unroll
        for (int k = 0; k < 16; k++) {
            float a0 = As[k][mfrag + 0], a1 = As[k][mfrag + 1];
            float a2 = As[k][mfrag + 2], a3 = As[k][mfrag + 3];
            float4 bv = *reinterpret_cast<const float4*>(&Bs[k][nfrag]);
            acc[0][0] = fmaf(a0, bv.x, acc[0][0]); acc[0][1] = fmaf(a0, bv.y, acc[0][1]);
            acc[0][2] = fmaf(a0, bv.z, acc[0][2]); acc[0][3] = fmaf(a0, bv.w, acc[0][3]);
            acc[1][0] = fmaf(a1, bv.x, acc[1][0]); acc[1][1] = fmaf(a1, bv.y, acc[1][1]);
            acc[1][2] = fmaf(a1, bv.z, acc[1][2]); acc[1][3] = fmaf(a1, bv.w, acc[1][3]);
            acc[2][0] = fmaf(a2, bv.x, acc[2][0]); acc[2][1] = fmaf(a2, bv.y, acc[2][1]);
            acc[2][2] = fmaf(a2, bv.z, acc[2][2]); acc[2][3] = fmaf(a2, bv.w, acc[2][3]);
            acc[3][0] = fmaf(a3, bv.x, acc[3][0]); acc[3][1] = fmaf(a3, bv.y, acc[3][1]);
            acc[3][2] = fmaf(a3, bv.z, acc[3][2]); acc[3][3] = fmaf(a3, bv.w, acc[3][3]);
        }
        __syncthreads();
    }
    #pragma unroll
    for (int e = 0; e < 4; e++) {
        size_t rowoff = (size_t)(bm + mfrag + e) * H_DIM;
        #pragma unroll
        for (int f = 0; f < 4; f++) {
            int n = bn + nfrag + f;
            outp[rowoff + n] = acc[e][f] + b[n];
        }
    }
}

// ---------------- persistent scan ----------------
__global__ void __launch_bounds__(TPB, 1)
scan_kernel(const float* __restrict__ Uz, const float* __restrict__ Ur,
            const float* __restrict__ Uh, const float* __restrict__ alpha,
            const float* __restrict__ hebb0, const float* __restrict__ eta_p,
            float* __restrict__ out_hT, float* __restrict__ out_hebb) {
    extern __shared__ float4 s_hebb4[];         // [RPT][CPT/4]
    const int tid = threadIdx.x;
    const int rt = blockIdx.x >> 1;             // 0..63
    const int ct = blockIdx.x & 1;              // 0..1
    const int i0 = rt * RPT;
    const int j0 = ct * CPT + tid * 4;          // first of 4 cols this thread owns

    const float eta = eta_p[0];
    const float om = 1.0f - eta;

    __shared__ float sh_h[RPT], sh_rh[RPT], sh_hm1[RPT];

    const int row = tid >> 3;                   // 0..31 (for reconstruction)
    const int seg = tid & 7;                    // 0..7

    // load hebb tile into SMEM (float4)
    for (int idx = tid; idx < RPT * (CPT / 4); idx += TPB) {
        int r = idx >> 8;                       // CPT/4 = 256
        int c = idx & 255;
        s_hebb4[idx] = *reinterpret_cast<const float4*>(
            hebb0 + (size_t)(i0 + r) * H_DIM + (size_t)ct * CPT + c * 4);
    }

    const float4* Uz4 = reinterpret_cast<const float4*>(Uz + (size_t)i0 * H_DIM) + (j0 >> 2);
    const float4* Ur4 = reinterpret_cast<const float4*>(Ur + (size_t)i0 * H_DIM) + (j0 >> 2);
    const float4* Uh4 = reinterpret_cast<const float4*>(Uh + (size_t)i0 * H_DIM) + (j0 >> 2);
    const float4* Al4 = reinterpret_cast<const float4*>(alpha + (size_t)i0 * H_DIM) + (j0 >> 2);
    const int ldq = H_DIM / 4;

    for (int t = 0; t < T_STEPS; t++) {
        const int p = t & 1;
        // ---- phase 1: reconstruct h_t rows (all 256 threads) ----
        if (t == 0) {
            if (tid < RPT) {
                sh_h[tid] = g_hbuf[i0 + tid];
                sh_hm1[tid] = 0.f;
            }
        } else {
            const int q = p ^ 1;
            const int i = i0 + row;
            float az = 0.f, ah = 0.f;
            #pragma unroll
            for (int k = 0; k < 8; k++) {
                az += g_Pz[q][seg * 8 + k][i];
                ah += g_Ph[q][seg * 8 + k][i];
            }
            #pragma unroll
            for (int off = 4; off > 0; off >>= 1) {
                az += __shfl_down_sync(0xffffffffu, az, off);
                ah += __shfl_down_sync(0xffffffffu, ah, off);
            }
            if (seg == 0) {
                az += g_xz[(size_t)(t - 1) * H_DIM + i];
                ah += g_xh[(size_t)(t - 1) * H_DIM + i];
                float z = sigm(az);
                float ht = tanhf(ah);
                float hp = g_hbuf[(size_t)(t - 1) * H_DIM + i];
                float h = (1.0f - z) * hp + z * ht;
                sh_h[row] = h;
                sh_hm1[row] = hp;
                if (ct == 0) g_hbuf[(size_t)t * H_DIM + i] = h;
            }
        }
        __syncthreads();

        // ---- z/r GEMV partials (float4, 4 cols/thread) ----
        {
            float4 az = {0.f, 0.f, 0.f, 0.f};
            float4 ar = {0.f, 0.f, 0.f, 0.f};
            #pragma unroll 4
            for (int i = 0; i < RPT; i++) {
                float hv = sh_h[i];
                float4 u = Uz4[(size_t)i * ldq];
                float4 v = Ur4[(size_t)i * ldq];
                az.x = fmaf(hv, u.x, az.x); az.y = fmaf(hv, u.y, az.y);
                az.z = fmaf(hv, u.z, az.z); az.w = fmaf(hv, u.w, az.w);
                ar.x = fmaf(hv, v.x, ar.x); ar.y = fmaf(hv, v.y, ar.y);
                ar.z = fmaf(hv, v.z, ar.z); ar.w = fmaf(hv, v.w, ar.w);
            }
            *reinterpret_cast<float4*>(&g_Pz[p][rt][j0]) = az;
            *reinterpret_cast<float4*>(&g_Pr[p][rt][j0]) = ar;
        }
        grid_barrier();

        // ---- phase 2: reconstruct r rows (all threads), then fused hebb+GEMV ----
        {
            const int i = i0 + row;
            float arv = 0.f;
            #pragma unroll
            for (int k = 0; k < 8; k++) arv += g_Pr[p][seg * 8 + k][i];
            #pragma unroll
            for (int off = 4; off > 0; off >>= 1)
                arv += __shfl_down_sync(0xffffffffu, arv, off);
            if (seg == 0) {
                arv += g_xr[(size_t)t * H_DIM + i];
                sh_rh[row] = sigm(arv) * sh_h[row];
            }
        }
        __syncthreads();
        {
            float4 acc = {0.f, 0.f, 0.f, 0.f};
            const float4 hj = *reinterpret_cast<const float4*>(
                g_hbuf + (size_t)t * H_DIM + j0);
            if (t > 0) {
                #pragma unroll 4
                for (int i = 0; i < RPT; i++) {
                    float rhv = sh_rh[i];
                    float em = eta * sh_hm1[i];
                    float4 v = s_hebb4[i * (CPT / 4) + tid];
                    v.x = fmaf(om, v.x, em * hj.x);
                    v.y = fmaf(om, v.y, em * hj.y);
                    v.z = fmaf(om, v.z, em * hj.z);
                    v.w = fmaf(om, v.w, em * hj.w);
                    s_hebb4[i * (CPT / 4) + tid] = v;
                    float4 u = Uh4[(size_t)i * ldq];
                    float4 a = Al4[(size_t)i * ldq];
                    acc.x = fmaf(rhv, fmaf(a.x, v.x, u.x), acc.x);
                    acc.y = fmaf(rhv, fmaf(a.y, v.y, u.y), acc.y);
                    acc.z = fmaf(rhv, fmaf(a.z, v.z, u.z), acc.z);
                    acc.w = fmaf(rhv, fmaf(a.w, v.w, u.w), acc.w);
                }
            } else {
                #pragma unroll 4
                for (int i = 0; i < RPT; i++) {
                    float rhv = sh_rh[i];
                    float4 v = s_hebb4[i * (CPT / 4) + tid];
                    float4 u = Uh4[(size_t)i * ldq];
                    float4 a = Al4[(size_t)i * ldq];
                    acc.x = fmaf(rhv, fmaf(a.x, v.x, u.x), acc.x);
                    acc.y = fmaf(rhv, fmaf(a.y, v.y, u.y), acc.y);
                    acc.z = fmaf(rhv, fmaf(a.z, v.z, u.z), acc.z);
                    acc.w = fmaf(rhv, fmaf(a.w, v.w, u.w), acc.w);
                }
            }
            *reinterpret_cast<float4*>(&g_Ph[p][rt][j0]) = acc;
        }
        grid_barrier();
    }

    // ---- finalize: h_T, hT out, hebbT out (apply last pending update) ----
    {
        const int q = (T_STEPS - 1) & 1;
        const int i = i0 + row;
        float az = 0.f, ah = 0.f;
        #pragma unroll
        for (int k = 0; k < 8; k++) {
            az += g_Pz[q][seg * 8 + k][i];
            ah += g_Ph[q][seg * 8 + k][i];
        }
        #pragma unroll
        for (int off = 4; off > 0; off >>= 1) {
            az += __shfl_down_sync(0xffffffffu, az, off);
            ah += __shfl_down_sync(0xffffffffu, ah, off);
        }
        if (seg == 0) {
            az += g_xz[(size_t)(T_STEPS - 1) * H_DIM + i];
            ah += g_xh[(size_t)(T_STEPS - 1) * H_DIM + i];
            float z = sigm(az);
            float ht = tanhf(ah);
            float hp = g_hbuf[(size_t)(T_STEPS - 1) * H_DIM + i];
            float h = (1.0f - z) * hp + z * ht;
            if (ct == 0) {
                g_hbuf[(size_t)T_STEPS * H_DIM + i] = h;
                out_hT[i] = h;
            }
            sh_hm1[row] = hp;   // h_{T-1}
        }
        grid_barrier();
        const float4 hj = *reinterpret_cast<const float4*>(
            g_hbuf + (size_t)T_STEPS * H_DIM + j0);
        for (int rl = 0; rl < RPT; rl++) {
            float em = eta * sh_hm1[rl];
            float4 v = s_hebb4[rl * (CPT / 4) + tid];
            v.x = fmaf(om, v.x, em * hj.x);
            v.y = fmaf(om, v.y, em * hj.y);
            v.z = fmaf(om, v.z, em * hj.z);
            v.w = fmaf(om, v.w, em * hj.w);
            *reinterpret_cast<float4*>(
                out_hebb + (size_t)(i0 + rl) * H_DIM + j0) = v;
        }
    }
}

// ---------------- output projection: y @ Wo + bo ----------------
__global__ void __launch_bounds__(256)
out_gemm_kernel(const float* __restrict__ Wo, const float* __restrict__ bo,
                float* __restrict__ out) {
    const int t = blockIdx.x;
    const int tid = threadIdx.x;
    const float* y = g_hbuf + (size_t)(t + 1) * H_DIM;   // y[t] = h_{t+1}
    float a0 = 0.f, a1 = 0.f, a2 = 0.f, a3 = 0.f;
    for (int jj = tid; jj < H_DIM; jj += 256) {
        float hv = y[jj];
        float4 w = *reinterpret_cast<const float4*>(Wo + (size_t)jj * OUT_DIM);
        a0 = fmaf(hv, w.x, a0); a1 = fmaf(hv, w.y, a1);
        a2 = fmaf(hv, w.z, a2); a3 = fmaf(hv, w.w, a3);
    }
    #pragma unroll
    for (int off = 16; off > 0; off >>= 1) {
        a0 += __shfl_down_sync(0xffffffffu, a0, off);
        a1 += __shfl_down_sync(0xffffffffu, a1, off);
        a2 += __shfl_down_sync(0xffffffffu, a2, off);
        a3 += __shfl_down_sync(0xffffffffu, a3, off);
    }
    __shared__ float red[8][4];
    const int wid = tid >> 5, lane = tid & 31;
    if (lane == 0) { red[wid][0] = a0; red[wid][1] = a1; red[wid][2] = a2; red[wid][3] = a3; }
    __syncthreads();
    if (tid < OUT_DIM) {
        float s = bo[tid];
        #pragma unroll
        for (int w = 0; w < 8; w++) s += red[w][tid];
        out[(size_t)t * OUT_DIM + tid] = s;
    }
}

// ---------------- JAX threefry2x32 (partitionable) / fold_in / categorical ----------------
__device__ __forceinline__ uint32_t rotl32(uint32_t x, int r) {
    return (x << r) | (x >> (32 - r));
}

__device__ __forceinline__ void threefry2x32(uint32_t k0, uint32_t k1,
                                             uint32_t x0, uint32_t x1,
                                             uint32_t& o0, uint32_t& o1) {
    uint32_t ks2 = k0 ^ k1 ^ 0x1BD11BDAu;
    uint32_t ks[3] = {k0, k1, ks2};
    const int r0[4] = {13, 15, 26, 6};
    const int r1[4] = {17, 29, 16, 24};
    x0 += k0; x1 += k1;
    #pragma unroll
    for (int d = 0; d < 5; d++) {
        const int* rr = (d & 1) ? r1 : r0;
        #pragma unroll
        for (int qv = 0; qv < 4; qv++) { x0 += x1; x1 = rotl32(x1, rr[qv]); x1 ^= x0; }
        x0 += ks[(d + 1) % 3];
        x1 += ks[(d + 2) % 3] + (uint32_t)(d + 1);
    }
    o0 = x0; o1 = x1;
}

__device__ __forceinline__ float gumbel_from_bits(uint32_t bits) {
    float f = __uint_as_float((bits >> 9) | 0x3f800000u) - 1.0f;
    const float tiny = 1.17549435e-38f;            // finfo(f32).tiny
    float u = f * (1.0f - tiny) + tiny;
    u = fmaxf(tiny, u);
    return -logf(-logf(u));
}

__global__ void action_kernel(const float* __restrict__ logits,
                              float* __restrict__ act_out,
                              const int* __restrict__ seed_p) {
    int t = blockIdx.x * blockDim.x + threadIdx.x;
    if (t >= T_STEPS) return;
    int seed = seed_p[0];
    uint32_t k0 = (seed < 0) ? 0xFFFFFFFFu : 0u;
    uint32_t k1 = (uint32_t)seed;
    uint32_t fk0, fk1;
    threefry2x32(k0, k1, 0u, 1u, fk0, fk1);        // fold_in(key, 1)

    uint32_t b[2];
    #pragma unroll
    for (int c = 0; c < 2; c++) {
        uint32_t m = 2u * (uint32_t)t + (uint32_t)c;
        uint32_t o0, o1;
        threefry2x32(fk0, fk1, 0u, m, o0, o1);
        b[c] = o0 ^ o1;
    }
    float v0 = logits[(size_t)t * OUT_DIM + 0] + gumbel_from_bits(b[0]);
    float v1 = logits[(size_t)t * OUT_DIM + 1] + gumbel_from_bits(b[1]);
    act_out[t] = (v1 > v0) ? 1.0f : 0.0f;
}

// ---------------- launch ----------------
extern "C" void kernel_launch(void* const* d_in, const int* in_sizes, int n_in,
                              void* d_out, int out_size) {
    const float* x     = (const float*)d_in[0];
    const float* h0    = (const float*)d_in[1];
    const float* hebb0 = (const float*)d_in[2];
    const float* Wz    = (const float*)d_in[3];
    const float* Uz    = (const float*)d_in[4];
    const float* bz    = (const float*)d_in[5];
    const float* Wr    = (const float*)d_in[6];
    const float* Ur    = (const float*)d_in[7];
    const float* br    = (const float*)d_in[8];
    const float* Wh    = (const float*)d_in[9];
    const float* Uh    = (const float*)d_in[10];
    const float* bh    = (const float*)d_in[11];
    const float* alpha = (const float*)d_in[12];
    const float* eta   = (const float*)d_in[13];
    const float* Wo    = (const float*)d_in[14];
    const float* bo    = (const float*)d_in[15];
    const int*   seed  = (const int*)d_in[16];
    float* out = (float*)d_out;

    float* out_output = out;
    float* out_action = out + (size_t)T_STEPS * OUT_DIM;
    float* out_hT     = out_action + T_STEPS;
    float* out_hebb   = out_hT + H_DIM;

    cudaFuncSetAttribute(scan_kernel,
                         cudaFuncAttributeMaxDynamicSharedMemorySize,
                         HEBB_SMEM_BYTES);

    init_kernel<<<(H_DIM + 255) / 256, 256>>>(h0);

    dim3 gproj(H_DIM / 64, T_STEPS / 64, 3);
    xproj_kernel<<<gproj, 256>>>(x, Wz, bz, Wr, br, Wh, bh);

    scan_kernel<<<NCTA, TPB, HEBB_SMEM_BYTES>>>(Uz, Ur, Uh, alpha, hebb0, eta,
                                                out_hT, out_hebb);

    out_gemm_kernel<<<T_STEPS, 256>>>(Wo, bo, out_output);

    action_kernel<<<(T_STEPS + 255) / 256, 256>>>(out_output, out_action, seed);
}

// round 6
// speedup vs baseline: 1.2728x; 1.0467x over previous
#include <cuda_runtime.h>
#include <cstdint>

#define T_STEPS 4096
#define IN_DIM  512
#define H_DIM   2048
#define OUT_DIM 4

#define NCTA 128
#define COLS_PER_CTA 16       // one warp per column
#define TPB2 512              // 16 warps
#define H4 (H_DIM/4)          // 512 float4 per column

// ---------------- device scratch (static; no allocs allowed) ----------------
__device__ float g_xz[(size_t)T_STEPS * H_DIM];
__device__ float g_xr[(size_t)T_STEPS * H_DIM];
__device__ float g_xh[(size_t)T_STEPS * H_DIM];
__device__ float g_hbuf[(size_t)(T_STEPS + 1) * H_DIM];
__device__ float g_rh[H_DIM];
__device__ float g_UzT[(size_t)H_DIM * H_DIM];
__device__ float g_UrT[(size_t)H_DIM * H_DIM];
__device__ float g_UhT[(size_t)H_DIM * H_DIM];
__device__ float g_AlT[(size_t)H_DIM * H_DIM];

__device__ unsigned g_barCnt = 0;
__device__ volatile unsigned g_barGen = 0;

__device__ __forceinline__ void grid_barrier() {
    __syncthreads();
    if (threadIdx.x == 0) {
        unsigned gen = g_barGen;
        __threadfence();
        unsigned arr = atomicAdd(&g_barCnt, 1u);
        if (arr == NCTA - 1) {
            g_barCnt = 0;
            __threadfence();
            g_barGen = gen + 1;
        } else {
            while (g_barGen == gen) { __nanosleep(32); }
            __threadfence();
        }
    }
    __syncthreads();
}

__device__ __forceinline__ float sigm(float x) { return 1.0f / (1.0f + expf(-x)); }

// ---------------- init: h0 -> g_hbuf[0] ----------------
__global__ void init_kernel(const float* __restrict__ h0) {
    int i = blockIdx.x * blockDim.x + threadIdx.x;
    if (i < H_DIM) g_hbuf[i] = h0[i];
}

// ---------------- transpose U matrices to column-major ----------------
__global__ void __launch_bounds__(256)
transpose_kernel(const float* __restrict__ Uz, const float* __restrict__ Ur,
                 const float* __restrict__ Uh, const float* __restrict__ Al) {
    __shared__ float tile[32][33];
    const int m = blockIdx.z;
    const float* src = (m == 0) ? Uz : (m == 1) ? Ur : (m == 2) ? Uh : Al;
    float* dst = (m == 0) ? g_UzT : (m == 1) ? g_UrT : (m == 2) ? g_UhT : g_AlT;
    const int x = blockIdx.x * 32 + threadIdx.x;
    const int y0 = blockIdx.y * 32;
    for (int r = threadIdx.y; r < 32; r += 8)
        tile[r][threadIdx.x] = src[(size_t)(y0 + r) * H_DIM + x];
    __syncthreads();
    const int x2 = blockIdx.y * 32 + threadIdx.x;
    const int y2 = blockIdx.x * 32;
    for (int r = threadIdx.y; r < 32; r += 8)
        dst[(size_t)(y2 + r) * H_DIM + x2] = tile[threadIdx.x][r];
}

// ---------------- input projections: x @ W_m + b_m ----------------
__global__ void __launch_bounds__(256)
xproj_kernel(const float* __restrict__ x,
             const float* __restrict__ Wz, const float* __restrict__ bz,
             const float* __restrict__ Wr, const float* __restrict__ br,
             const float* __restrict__ Wh, const float* __restrict__ bh) {
    const int mat = blockIdx.z;
    const float* W = (mat == 0) ? Wz : (mat == 1) ? Wr : Wh;
    const float* b = (mat == 0) ? bz : (mat == 1) ? br : bh;
    float* outp    = (mat == 0) ? g_xz : (mat == 1) ? g_xr : g_xh;

    const int bn = blockIdx.x * 64;
    const int bm = blockIdx.y * 64;

    __shared__ float As[16][65];
    __shared__ float Bs[16][64];

    const int tid = threadIdx.x;
    const int ty = tid >> 4, tx = tid & 15;
    const int mfrag = ty * 4, nfrag = tx * 4;

    float acc[4][4] = {};

    for (int k0 = 0; k0 < IN_DIM; k0 += 16) {
        {
            int row = tid >> 2, q = tid & 3;
            float4 v = *reinterpret_cast<const float4*>(
                x + (size_t)(bm + row) * IN_DIM + k0 + q * 4);
            As[q * 4 + 0][row] = v.x; As[q * 4 + 1][row] = v.y;
            As[q * 4 + 2][row] = v.z; As[q * 4 + 3][row] = v.w;
            int krow = tid >> 4, c4 = (tid & 15) * 4;
            float4 w = *reinterpret_cast<const float4*>(
                W + (size_t)(k0 + krow) * H_DIM + bn + c4);
            *reinterpret_cast<float4*>(&Bs[krow][c4]) = w;
        }
        __syncthreads();
        #pragma unroll
        for (int k = 0; k < 16; k++) {
            float a0 = As[k][mfrag + 0], a1 = As[k][mfrag + 1];
            float a2 = As[k][mfrag + 2], a3 = As[k][mfrag + 3];
            float4 bv = *reinterpret_cast<const float4*>(&Bs[k][nfrag]);
            acc[0][0] = fmaf(a0, bv.x, acc[0][0]); acc[0][1] = fmaf(a0, bv.y, acc[0][1]);
            acc[0][2] = fmaf(a0, bv.z, acc[0][2]); acc[0][3] = fmaf(a0, bv.w, acc[0][3]);
            acc[1][0] = fmaf(a1, bv.x, acc[1][0]); acc[1][1] = fmaf(a1, bv.y, acc[1][1]);
            acc[1][2] = fmaf(a1, bv.z, acc[1][2]); acc[1][3] = fmaf(a1, bv.w, acc[1][3]);
            acc[2][0] = fmaf(a2, bv.x, acc[2][0]); acc[2][1] = fmaf(a2, bv.y, acc[2][1]);
            acc[2][2] = fmaf(a2, bv.z, acc[2][2]); acc[2][3] = fmaf(a2, bv.w, acc[2][3]);
            acc[3][0] = fmaf(a3, bv.x, acc[3][0]); acc[3][1] = fmaf(a3, bv.y, acc[3][1]);
            acc[3][2] = fmaf(a3, bv.z, acc[3][2]); acc[3][3] = fmaf(a3, bv.w, acc[3][3]);
        }
        __syncthreads();
    }
    #pragma unroll
    for (int e = 0; e < 4; e++) {
        size_t rowoff = (size_t)(bm + mfrag + e) * H_DIM;
        #pragma unroll
        for (int f = 0; f < 4; f++) {
            int n = bn + nfrag + f;
            outp[rowoff + n] = acc[e][f] + b[n];
        }
    }
}

// ---------------- persistent scan: column ownership, warp per column ----------------
// smem: s_hebb [16 cols][2048 rows] col-major, s_h[2][2048], s_rh[2048]
#define SCAN_SMEM_BYTES ((16 * H_DIM + 2 * H_DIM + H_DIM) * 4)

__global__ void __launch_bounds__(TPB2, 1)
scan_kernel(const float* __restrict__ hebb0, const float* __restrict__ eta_p,
            float* __restrict__ out_hT, float* __restrict__ out_hebb) {
    extern __shared__ float smem[];
    float* s_hebb = smem;                       // 16*2048
    float* s_h    = smem + 16 * H_DIM;          // 2*2048 (ping-pong h_t / h_{t-1})
    float* s_rh   = smem + 18 * H_DIM;          // 2048

    const int tid = threadIdx.x;
    const int w = tid >> 5;                     // warp 0..15 = local column
    const int lane = tid & 31;
    const int j0 = blockIdx.x * COLS_PER_CTA;
    const int j = j0 + w;                       // global column owned by this warp

    const float eta = eta_p[0];
    const float om = 1.0f - eta;

    // load hebb tile (transposing into col-major SMEM)
    for (int i = tid; i < H_DIM; i += TPB2) {
        const float4* src = reinterpret_cast<const float4*>(
            hebb0 + (size_t)i * H_DIM + j0);
        float4 a = src[0], b = src[1], c = src[2], d = src[3];
        s_hebb[0 * H_DIM + i] = a.x;  s_hebb[1 * H_DIM + i] = a.y;
        s_hebb[2 * H_DIM + i] = a.z;  s_hebb[3 * H_DIM + i] = a.w;
        s_hebb[4 * H_DIM + i] = b.x;  s_hebb[5 * H_DIM + i] = b.y;
        s_hebb[6 * H_DIM + i] = b.z;  s_hebb[7 * H_DIM + i] = b.w;
        s_hebb[8 * H_DIM + i] = c.x;  s_hebb[9 * H_DIM + i] = c.y;
        s_hebb[10 * H_DIM + i] = c.z; s_hebb[11 * H_DIM + i] = c.w;
        s_hebb[12 * H_DIM + i] = d.x; s_hebb[13 * H_DIM + i] = d.y;
        s_hebb[14 * H_DIM + i] = d.z; s_hebb[15 * H_DIM + i] = d.w;
    }

    const float4* uz4 = reinterpret_cast<const float4*>(g_UzT) + (size_t)j * H4;
    const float4* ur4 = reinterpret_cast<const float4*>(g_UrT) + (size_t)j * H4;
    const float4* uh4 = reinterpret_cast<const float4*>(g_UhT) + (size_t)j * H4;
    const float4* al4 = reinterpret_cast<const float4*>(g_AlT) + (size_t)j * H4;
    float4* hb4 = reinterpret_cast<float4*>(s_hebb + (size_t)w * H_DIM);
    const float4* rh4 = reinterpret_cast<const float4*>(s_rh);

    float hlast = 0.f;

    for (int t = 0; t < T_STEPS; t++) {
        const int cur = t & 1;
        // ---- phase A: load full h_t, compute z/r for owned column ----
        reinterpret_cast<float4*>(s_h + (size_t)cur * H_DIM)[tid] =
            reinterpret_cast<const float4*>(g_hbuf + (size_t)t * H_DIM)[tid];
        __syncthreads();

        const float4* h4 = reinterpret_cast<const float4*>(s_h + (size_t)cur * H_DIM);
        float az = 0.f, ar = 0.f;
        #pragma unroll 4
        for (int k = lane; k < H4; k += 32) {
            float4 u = uz4[k], v = ur4[k], hv = h4[k];
            az = fmaf(u.x, hv.x, az); az = fmaf(u.y, hv.y, az);
            az = fmaf(u.z, hv.z, az); az = fmaf(u.w, hv.w, az);
            ar = fmaf(v.x, hv.x, ar); ar = fmaf(v.y, hv.y, ar);
            ar = fmaf(v.z, hv.z, ar); ar = fmaf(v.w, hv.w, ar);
        }
        #pragma unroll
        for (int off = 16; off > 0; off >>= 1) {
            az += __shfl_xor_sync(0xffffffffu, az, off);
            ar += __shfl_xor_sync(0xffffffffu, ar, off);
        }
        const float z = sigm(g_xz[(size_t)t * H_DIM + j] + az);
        const float r = sigm(g_xr[(size_t)t * H_DIM + j] + ar);
        const float htj = s_h[(size_t)cur * H_DIM + j];
        if (lane == 0) g_rh[j] = r * htj;
        grid_barrier();

        // ---- phase B: load full rh, fused lazy-hebb + (Uh + alpha*hebb) column dot ----
        reinterpret_cast<float4*>(s_rh)[tid] =
            reinterpret_cast<const float4*>(g_rh)[tid];
        __syncthreads();

        float acc = 0.f;
        if (t > 0) {
            const float4* hp4 = reinterpret_cast<const float4*>(
                s_h + (size_t)(cur ^ 1) * H_DIM);
            const float emj = eta * htj;
            #pragma unroll 4
            for (int k = lane; k < H4; k += 32) {
                float4 hb = hb4[k];
                float4 hp = hp4[k];
                hb.x = fmaf(om, hb.x, emj * hp.x);
                hb.y = fmaf(om, hb.y, emj * hp.y);
                hb.z = fmaf(om, hb.z, emj * hp.z);
                hb.w = fmaf(om, hb.w, emj * hp.w);
                hb4[k] = hb;
                float4 u = uh4[k], a = al4[k], rr = rh4[k];
                acc = fmaf(rr.x, fmaf(a.x, hb.x, u.x), acc);
                acc = fmaf(rr.y, fmaf(a.y, hb.y, u.y), acc);
                acc = fmaf(rr.z, fmaf(a.z, hb.z, u.z), acc);
                acc = fmaf(rr.w, fmaf(a.w, hb.w, u.w), acc);
            }
        } else {
            #pragma unroll 4
            for (int k = lane; k < H4; k += 32) {
                float4 hb = hb4[k];
                float4 u = uh4[k], a = al4[k], rr = rh4[k];
                acc = fmaf(rr.x, fmaf(a.x, hb.x, u.x), acc);
                acc = fmaf(rr.y, fmaf(a.y, hb.y, u.y), acc);
                acc = fmaf(rr.z, fmaf(a.z, hb.z, u.z), acc);
                acc = fmaf(rr.w, fmaf(a.w, hb.w, u.w), acc);
            }
        }
        #pragma unroll
        for (int off = 16; off > 0; off >>= 1)
            acc += __shfl_xor_sync(0xffffffffu, acc, off);

        const float htil = tanhf(g_xh[(size_t)t * H_DIM + j] + acc);
        const float hnew = (1.0f - z) * htj + z * htil;
        if (lane == 0) g_hbuf[(size_t)(t + 1) * H_DIM + j] = hnew;
        hlast = hnew;
        grid_barrier();
    }

    // ---- finalize ----
    if (lane == 0) out_hT[j] = hlast;
    {
        // apply final pending update: hebb_T = om*hebb + eta*outer(h_{T-1}, h_T)
        // h_{T-1} is in s_h[(T-1)&1] = s_h[1]
        const float4* hp4 = reinterpret_cast<const float4*>(s_h + H_DIM);
        const float emf = eta * hlast;
        for (int k = lane; k < H4; k += 32) {
            float4 hb = hb4[k];
            float4 hp = hp4[k];
            hb.x = fmaf(om, hb.x, emf * hp.x);
            hb.y = fmaf(om, hb.y, emf * hp.y);
            hb.z = fmaf(om, hb.z, emf * hp.z);
            hb.w = fmaf(om, hb.w, emf * hp.w);
            hb4[k] = hb;
        }
    }
    __syncthreads();
    // cooperative transposed write-out (64B contiguous per row)
    for (int i = tid; i < H_DIM; i += TPB2) {
        float tmp[16];
        #pragma unroll
        for (int c = 0; c < 16; c++) tmp[c] = s_hebb[(size_t)c * H_DIM + i];
        float4* dst = reinterpret_cast<float4*>(out_hebb + (size_t)i * H_DIM + j0);
        dst[0] = make_float4(tmp[0], tmp[1], tmp[2], tmp[3]);
        dst[1] = make_float4(tmp[4], tmp[5], tmp[6], tmp[7]);
        dst[2] = make_float4(tmp[8], tmp[9], tmp[10], tmp[11]);
        dst[3] = make_float4(tmp[12], tmp[13], tmp[14], tmp[15]);
    }
}

// ---------------- output projection: y @ Wo + bo ----------------
__global__ void __launch_bounds__(256)
out_gemm_kernel(const float* __restrict__ Wo, const float* __restrict__ bo,
                float* __restrict__ out) {
    const int t = blockIdx.x;
    const int tid = threadIdx.x;
    const float* y = g_hbuf + (size_t)(t + 1) * H_DIM;
    float a0 = 0.f, a1 = 0.f, a2 = 0.f, a3 = 0.f;
    for (int jj = tid; jj < H_DIM; jj += 256) {
        float hv = y[jj];
        float4 w = *reinterpret_cast<const float4*>(Wo + (size_t)jj * OUT_DIM);
        a0 = fmaf(hv, w.x, a0); a1 = fmaf(hv, w.y, a1);
        a2 = fmaf(hv, w.z, a2); a3 = fmaf(hv, w.w, a3);
    }
    #pragma unroll
    for (int off = 16; off > 0; off >>= 1) {
        a0 += __shfl_down_sync(0xffffffffu, a0, off);
        a1 += __shfl_down_sync(0xffffffffu, a1, off);
        a2 += __shfl_down_sync(0xffffffffu, a2, off);
        a3 += __shfl_down_sync(0xffffffffu, a3, off);
    }
    __shared__ float red[8][4];
    const int wid = tid >> 5, lane = tid & 31;
    if (lane == 0) { red[wid][0] = a0; red[wid][1] = a1; red[wid][2] = a2; red[wid][3] = a3; }
    __syncthreads();
    if (tid < OUT_DIM) {
        float s = bo[tid];
        #pragma unroll
        for (int w = 0; w < 8; w++) s += red[w][tid];
        out[(size_t)t * OUT_DIM + tid] = s;
    }
}

// ---------------- JAX threefry2x32 (partitionable) / fold_in / categorical ----------------
__device__ __forceinline__ uint32_t rotl32(uint32_t x, int r) {
    return (x << r) | (x >> (32 - r));
}

__device__ __forceinline__ void threefry2x32(uint32_t k0, uint32_t k1,
                                             uint32_t x0, uint32_t x1,
                                             uint32_t& o0, uint32_t& o1) {
    uint32_t ks2 = k0 ^ k1 ^ 0x1BD11BDAu;
    uint32_t ks[3] = {k0, k1, ks2};
    const int r0[4] = {13, 15, 26, 6};
    const int r1[4] = {17, 29, 16, 24};
    x0 += k0; x1 += k1;
    #pragma unroll
    for (int d = 0; d < 5; d++) {
        const int* rr = (d & 1) ? r1 : r0;
        #pragma unroll
        for (int qv = 0; qv < 4; qv++) { x0 += x1; x1 = rotl32(x1, rr[qv]); x1 ^= x0; }
        x0 += ks[(d + 1) % 3];
        x1 += ks[(d + 2) % 3] + (uint32_t)(d + 1);
    }
    o0 = x0; o1 = x1;
}

__device__ __forceinline__ float gumbel_from_bits(uint32_t bits) {
    float f = __uint_as_float((bits >> 9) | 0x3f800000u) - 1.0f;
    const float tiny = 1.17549435e-38f;
    float u = f * (1.0f - tiny) + tiny;
    u = fmaxf(tiny, u);
    return -logf(-logf(u));
}

__global__ void action_kernel(const float* __restrict__ logits,
                              float* __restrict__ act_out,
                              const int* __restrict__ seed_p) {
    int t = blockIdx.x * blockDim.x + threadIdx.x;
    if (t >= T_STEPS) return;
    int seed = seed_p[0];
    uint32_t k0 = (seed < 0) ? 0xFFFFFFFFu : 0u;
    uint32_t k1 = (uint32_t)seed;
    uint32_t fk0, fk1;
    threefry2x32(k0, k1, 0u, 1u, fk0, fk1);        // fold_in(key, 1)

    uint32_t b[2];
    #pragma unroll
    for (int c = 0; c < 2; c++) {
        uint32_t m = 2u * (uint32_t)t + (uint32_t)c;
        uint32_t o0, o1;
        threefry2x32(fk0, fk1, 0u, m, o0, o1);
        b[c] = o0 ^ o1;
    }
    float v0 = logits[(size_t)t * OUT_DIM + 0] + gumbel_from_bits(b[0]);
    float v1 = logits[(size_t)t * OUT_DIM + 1] + gumbel_from_bits(b[1]);
    act_out[t] = (v1 > v0) ? 1.0f : 0.0f;
}

// ---------------- launch ----------------
extern "C" void kernel_launch(void* const* d_in, const int* in_sizes, int n_in,
                              void* d_out, int out_size) {
    const float* x     = (const float*)d_in[0];
    const float* h0    = (const float*)d_in[1];
    const float* hebb0 = (const float*)d_in[2];
    const float* Wz    = (const float*)d_in[3];
    const float* Uz    = (const float*)d_in[4];
    const float* bz    = (const float*)d_in[5];
    const float* Wr    = (const float*)d_in[6];
    const float* Ur    = (const float*)d_in[7];
    const float* br    = (const float*)d_in[8];
    const float* Wh    = (const float*)d_in[9];
    const float* Uh    = (const float*)d_in[10];
    const float* bh    = (const float*)d_in[11];
    const float* alpha = (const float*)d_in[12];
    const float* eta   = (const float*)d_in[13];
    const float* Wo    = (const float*)d_in[14];
    const float* bo    = (const float*)d_in[15];
    const int*   seed  = (const int*)d_in[16];
    float* out = (float*)d_out;

    float* out_output = out;
    float* out_action = out + (size_t)T_STEPS * OUT_DIM;
    float* out_hT     = out_action + T_STEPS;
    float* out_hebb   = out_hT + H_DIM;

    cudaFuncSetAttribute(scan_kernel,
                         cudaFuncAttributeMaxDynamicSharedMemorySize,
                         SCAN_SMEM_BYTES);

    init_kernel<<<(H_DIM + 255) / 256, 256>>>(h0);

    dim3 gtr(H_DIM / 32, H_DIM / 32, 4);
    transpose_kernel<<<gtr, dim3(32, 8)>>>(Uz, Ur, Uh, alpha);

    dim3 gproj(H_DIM / 64, T_STEPS / 64, 3);
    xproj_kernel<<<gproj, 256>>>(x, Wz, bz, Wr, br, Wh, bh);

    scan_kernel<<<NCTA, TPB2, SCAN_SMEM_BYTES>>>(hebb0, eta, out_hT, out_hebb);

    out_gemm_kernel<<<T_STEPS, 256>>>(Wo, bo, out_output);

    action_kernel<<<(T_STEPS + 255) / 256, 256>>>(out_output, out_action, seed);
}